// round 10
// baseline (speedup 1.0000x reference)
#include <cuda_runtime.h>
#include <math.h>
#include <limits.h>

#define TT 4096
#define NN 262144
#define BB 128
#define NB 8192
#define CAP 2048

__device__ float g_xm[BB*TT];
__device__ float g_cs[BB*64];
__device__ float g_cq[BB*64];
__device__ int2  g_qi[BB][6];
__device__ int   g_qc[BB][3];
__device__ float g_cand[BB][3][CAP];
__constant__ int c_rk[6] = {65535,65536,131071,131072,196607,196608};

__device__ __forceinline__ float wsum(float v){
#pragma unroll
  for(int o=16;o;o>>=1) v += __shfl_down_sync(~0u,v,o);
  return v;
}
__device__ __forceinline__ float bsum(float v, float* sr){
  v=wsum(v);
  if((threadIdx.x&31)==0) sr[threadIdx.x>>5]=v;
  __syncthreads();
  if(threadIdx.x==0){ float a=0; int nw=blockDim.x>>5; for(int i=0;i<nw;i++) a+=sr[i]; sr[0]=a; }
  __syncthreads();
  float r=sr[0]; __syncthreads();
  return r;
}
__device__ __forceinline__ int binf(float v){
  int b=(int)((v+8.f)*512.f);
  return b<0?0:(b>NB-1?NB-1:b);
}
__device__ __forceinline__ unsigned long long pack2(float x,float y){
  unsigned long long r; asm("mov.b64 %0,{%1,%2};":"=l"(r):"f"(x),"f"(y)); return r;
}
__device__ __forceinline__ void unpack2(unsigned long long v,float&x,float&y){
  asm("mov.b64 {%0,%1},%2;":"=f"(x),"=f"(y):"l"(v));
}
__device__ __forceinline__ void ffma2(unsigned long long&d,unsigned long long a,unsigned long long b){
  asm("fma.rn.f32x2 %0,%1,%2,%0;":"+l"(d):"l"(a),"l"(b));
}

// ---------------- k1: fused streaming pass ----------------
__global__ __launch_bounds__(256) void k1(const float* __restrict__ x,
                                          const float* __restrict__ mk,
                                          float* __restrict__ out){
  __shared__ unsigned hist[NB];
  __shared__ float sA[8][64], sB[8][64];
  __shared__ int so[8], so2[8], sf;
  __shared__ unsigned sc[256];
  int tid=threadIdx.x, w=tid>>5, l=tid&31, b=blockIdx.x;
  const float2* xb=(const float2*)x + (size_t)b*(NN/2);
  const float2* mb=(const float2*)mk + (size_t)b*(NN/2);
  for(int i=tid;i<NB;i+=256) hist[i]=0u;
  if(tid==0){ sf=INT_MAX; g_qc[b][0]=0; g_qc[b][1]=0; g_qc[b][2]=0; }
  __syncthreads();
  float cs0=0,cs1=0,cq0=0,cq1=0,S1=0,S2=0,S3=0,S4=0,AC=0;
  int ob=0,ob2=0,fm=INT_MAX;
  float2 pv=make_float2(0.f,0.f);
  if(w>0) pv = xb[(w*512-1)*32+l];
  for(int it=0; it<512; ++it){
    int t = w*512+it;
    float2 v = xb[t*32+l];
    float2 m = mb[t*32+l];
    float rs = wsum(v.x+v.y);
    if(l==0) g_xm[b*TT+t]=rs*(1.f/64.f);
    cs0+=v.x; cs1+=v.y; cq0+=v.x*v.x; cq1+=v.y*v.y;
    float a2=v.x*v.x, b2=v.y*v.y;
    S1+=v.x+v.y; S2+=a2+b2; S3+=a2*v.x+b2*v.y; S4+=a2*a2+b2*b2;
    if(t>0) AC += pv.x*v.x + pv.y*v.y;
    pv=v;
    atomicAdd(&hist[binf(v.x)],1u);
    atomicAdd(&hist[binf(v.y)],1u);
    float ms = wsum(m.x+m.y);
    if(l==0){ int o=(int)(ms+0.5f); ob+=o; ob2+=o*o; if(o>0&&t<fm) fm=t; }
  }
  sA[w][2*l]=cs0; sA[w][2*l+1]=cs1; sB[w][2*l]=cq0; sB[w][2*l+1]=cq1;
  if(l==0){ so[w]=ob; so2[w]=ob2; atomicMin(&sf,fm); }
  __syncthreads();
  if(tid<64){ float a=0,q=0;
    for(int i=0;i<8;i++){a+=sA[i][tid];q+=sB[i][tid];}
    g_cs[b*64+tid]=a; g_cq[b*64+tid]=q; }
  float r1=wsum(S1), r2=wsum(S2), r3=wsum(S3), r4=wsum(S4), r5=wsum(AC);
  __syncthreads();
  if(l==0){ sA[0][w]=r1; sA[1][w]=r2; sA[2][w]=r3; sA[3][w]=r4; sA[4][w]=r5; }
  __syncthreads();
  if(tid==0){
    double s1=0,s2=0,s3=0,s4=0,ac=0;
    for(int i=0;i<8;i++){ s1+=sA[0][i]; s2+=sA[1][i]; s3+=sA[2][i]; s4+=sA[3][i]; ac+=sA[4][i]; }
    double n=262144.0, mu=s1/n;
    double m2=s2/n-mu*mu;
    double m3=s3/n-3.0*mu*(s2/n)+2.0*mu*mu*mu;
    double m4=s4/n-4.0*mu*(s3/n)+6.0*mu*mu*(s2/n)-3.0*mu*mu*mu*mu;
    out[b*17+0]=(float)(ac/262080.0);
    out[b*17+4]=(float)(m3/(pow(m2,1.5)+1e-8));
    out[b*17+5]=(float)(m4/(m2*m2+1e-8));
    long long t1=0,t2=0;
    for(int i=0;i<8;i++){t1+=so[i];t2+=so2[i];}
    out[b*17+12]=(float)(1.0-(double)t1/(262144.0+1e-8));
    double dv=64.0+1e-8, m=(double)t1/dv/4096.0;
    out[b*17+13]=(float)(((double)t2/(dv*dv)-4096.0*m*m)/4095.0);
    out[b*17+14]=(sf==INT_MAX)?0.f:(float)((double)sf/4096.0);
  }
  unsigned lc=0;
  for(int i=0;i<32;i++) lc+=hist[tid*32+i];
  sc[tid]=lc; __syncthreads();
  if(tid==0){ unsigned run=0; for(int i=0;i<256;i++){unsigned c=sc[i]; sc[i]=run; run+=c;} }
  __syncthreads();
  unsigned cum=sc[tid];
  for(int i=0;i<32;i++){
    unsigned c=hist[tid*32+i];
    for(int q=0;q<6;q++){ unsigned r=(unsigned)c_rk[q];
      if(r>=cum && r<cum+c) g_qi[b][q]=make_int2(tid*32+i,(int)cum); }
    cum+=c;
  }
}

// ---------------- k2: quantile candidate gather ----------------
__global__ __launch_bounds__(256) void k2(const float* __restrict__ x){
  int b=blockIdx.x;
  int lo[3],hi[3];
  for(int q=0;q<3;q++){ lo[q]=g_qi[b][2*q].x; hi[q]=g_qi[b][2*q+1].x; }
  const float4* xb=(const float4*)x + (size_t)b*(NN/4);
  for(int i=blockIdx.y*256+threadIdx.x; i<NN/4; i+=gridDim.y*256){
    float4 v=xb[i];
    float vv[4]={v.x,v.y,v.z,v.w};
    for(int j=0;j<4;j++){
      int bn=binf(vv[j]);
      for(int q=0;q<3;q++) if(bn>=lo[q]&&bn<=hi[q]){
        int p=atomicAdd(&g_qc[b][q],1);
        if(p<CAP) g_cand[b][q][p]=vv[j];
      }
    }
  }
}

// ---------------- k3: exact rank select + interp ----------------
__global__ __launch_bounds__(256) void k3(float* __restrict__ out){
  __shared__ float c[CAP];
  __shared__ float v0s,v1s;
  int b=blockIdx.x, q=blockIdx.y, tid=threadIdx.x;
  int n=min(g_qc[b][q],CAP);
  if(tid==0){ v0s=0.f; v1s=0.f; }
  for(int i=tid;i<n;i+=256) c[i]=g_cand[b][q][i];
  __syncthreads();
  int base=g_qi[b][2*q].y;
  int j0=c_rk[2*q]-base, j1=c_rk[2*q]+1-base;
  for(int i=tid;i<n;i+=256){
    float vi=c[i]; int r=0;
    for(int j=0;j<n;j++){ float vj=c[j]; r += (vj<vi)||(vj==vi&&j<i); }
    if(r==j0) v0s=vi;
    if(r==j1) v1s=vi;
  }
  __syncthreads();
  if(tid==0){
    const float fr[3]={0.75f,0.5f,0.25f};
    out[b*17+6+q]=v0s+fr[q]*(v1s-v0s);
  }
}

// ---------------- k4: time-domain stats + FFT features ----------------
__global__ __launch_bounds__(512) void k4(float* __restrict__ out){
  __shared__ float xr[4096], xi[4096];
  __shared__ float sred[16];
  __shared__ int sidx[16];
  int tid=threadIdx.x, b=blockIdx.x;
  const float* gm=&g_xm[(size_t)b*4096];
  float a=0;
  for(int i=tid;i<4096;i+=512) a+=gm[i];
  float mean=bsum(a,sred)*(1.f/4096.f);
  float num=0;
  for(int i=tid;i<4096;i+=512) num+=((float)i-2047.5f)*gm[i];
  num=bsum(num,sred);
  float roc=0,pk=0,zc=0;
  for(int i=tid+1;i<4096;i+=512){
    float d1=gm[i]-gm[i-1];
    roc+=fabsf(d1);
    zc += ((gm[i]-mean)*(gm[i-1]-mean)<0.f)?1.f:0.f;
    if(i<4095){ float d2=gm[i+1]-gm[i]; pk += (d2*d1<0.f)?1.f:0.f; }
  }
  roc=bsum(roc,sred); pk=bsum(pk,sred); zc=bsum(zc,sred);
  if(tid==0){
    out[b*17+1]=num/(5726622720.f+1e-8f);
    out[b*17+9]=pk/4094.f;
    out[b*17+10]=zc/4095.f;
    out[b*17+11]=roc/4095.f;
  }
  for(int i=tid;i<4096;i+=512){ xr[__brev((unsigned)i)>>20]=gm[i]; xi[i]=0.f; }
  __syncthreads();
  for(int st=1; st<=12; ++st){
    int len=1<<st, h=len>>1;
    for(int i=tid;i<2048;i+=512){
      int j=i&(h-1);
      int p=((i>>(st-1))<<st)+j;
      float ang=-6.2831853071795864f*(float)j/(float)len;
      float sv,cv; sincosf(ang,&sv,&cv);
      float ar=xr[p+h], ai=xi[p+h];
      float tr=cv*ar-sv*ai, ti=cv*ai+sv*ar;
      xr[p+h]=xr[p]-tr; xi[p+h]=xi[p]-ti;
      xr[p]+=tr; xi[p]+=ti;
    }
    __syncthreads();
  }
  float ps=0, mx=-1.f; int mi=0;
  for(int k=tid;k<=2048;k+=512){
    float p=xr[k]*xr[k]+xi[k]*xi[k];
    ps+=p;
    if(p>mx){mx=p;mi=k;}
    xr[k]=p;
  }
  float S=bsum(ps,sred);
#pragma unroll
  for(int o=16;o;o>>=1){
    float ov=__shfl_down_sync(~0u,mx,o);
    int oi=__shfl_down_sync(~0u,mi,o);
    if(ov>mx||(ov==mx&&oi<mi)){mx=ov;mi=oi;}
  }
  if((tid&31)==0){ sred[tid>>5]=mx; sidx[tid>>5]=mi; }
  __syncthreads();
  if(tid==0){
    for(int i=1;i<16;i++)
      if(sred[i]>sred[0]||(sred[i]==sred[0]&&sidx[i]<sidx[0])){sred[0]=sred[i];sidx[0]=sidx[i];}
    out[b*17+2]=(float)sidx[0]/2048.f;
  }
  __syncthreads();
  float ent=0;
  for(int k=tid;k<=2048;k+=512){
    float pn=xr[k]/(S+1e-8f);
    ent -= pn*logf(pn+1e-8f);
  }
  ent=bsum(ent,sred);
  if(tid==0) out[b*17+3]=ent;
}

// ---------------- k5: gram + mean_corr + power iteration ----------------
__global__ __launch_bounds__(256) void k5(const float* __restrict__ x,
                                          float* __restrict__ out){
  __shared__ float ch[64][64];
  __shared__ float G[64][64];
  __shared__ float scs[64], sq[64], sstd[64], v[64], sr[8];
  int tid=threadIdx.x, b=blockIdx.x;
  int hf=tid>>7, t2=tid&127;
  int ri=(t2&15)*4, cjp=(t2>>4)*4;
  unsigned long long acc[16];
#pragma unroll
  for(int i=0;i<16;i++) acc[i]=pack2(0.f,0.f);
  const float4* xb=(const float4*)x + (size_t)b*(NN/4);
  for(int it=0; it<64; ++it){
    __syncthreads();
    for(int i=tid;i<1024;i+=256) ((float4*)&ch[0][0])[i]=xb[it*1024+i];
    __syncthreads();
    const float* basep=&ch[hf*32][0];
#pragma unroll 4
    for(int k=0;k<32;++k){
      const float* row=basep+k*64;
      unsigned long long a0=pack2(row[ri],row[ri]);
      unsigned long long a1=pack2(row[ri+1],row[ri+1]);
      unsigned long long a2=pack2(row[ri+2],row[ri+2]);
      unsigned long long a3=pack2(row[ri+3],row[ri+3]);
      const unsigned long long* rp=(const unsigned long long*)row;
      unsigned long long b0=rp[cjp],b1=rp[cjp+1],b2=rp[cjp+2],b3=rp[cjp+3];
      ffma2(acc[0],a0,b0);  ffma2(acc[1],a0,b1);  ffma2(acc[2],a0,b2);  ffma2(acc[3],a0,b3);
      ffma2(acc[4],a1,b0);  ffma2(acc[5],a1,b1);  ffma2(acc[6],a1,b2);  ffma2(acc[7],a1,b3);
      ffma2(acc[8],a2,b0);  ffma2(acc[9],a2,b1);  ffma2(acc[10],a2,b2); ffma2(acc[11],a2,b3);
      ffma2(acc[12],a3,b0); ffma2(acc[13],a3,b1); ffma2(acc[14],a3,b2); ffma2(acc[15],a3,b3);
    }
  }
  __syncthreads();
  if(hf==0)
    for(int r=0;r<4;r++) for(int c=0;c<4;c++){
      float e0,e1; unpack2(acc[r*4+c],e0,e1);
      G[ri+r][cjp*2+2*c]=e0; G[ri+r][cjp*2+2*c+1]=e1; }
  __syncthreads();
  if(hf==1)
    for(int r=0;r<4;r++) for(int c=0;c<4;c++){
      float e0,e1; unpack2(acc[r*4+c],e0,e1);
      G[ri+r][cjp*2+2*c]+=e0; G[ri+r][cjp*2+2*c+1]+=e1; }
  if(tid<64){ scs[tid]=g_cs[b*64+tid]; sq[tid]=g_cq[b*64+tid]; }
  __syncthreads();
  for(int i=tid;i<4096;i+=256){
    int d=i>>6,e=i&63;
    G[d][e]-=scs[d]*scs[e]*(1.f/4096.f);
  }
  if(tid<64) sstd[tid]=sqrtf((sq[tid]-scs[tid]*scs[tid]*(1.f/4096.f))*(1.f/4095.f));
  __syncthreads();
  float mc=0;
  for(int i=tid;i<4096;i+=256){
    int d=i>>6,e=i&63;
    if(d!=e) mc += (G[d][e]/(4095.f+1e-8f))/(sstd[d]*sstd[e]+1e-8f);
  }
  mc=bsum(mc,sr);
  if(tid==0) out[b*17+15]=mc/(4032.f+1e-8f);
  // --- shifted, scaled power iteration (overflow-proof) ---
  // shift sigma=2500 < lambda_min(G) keeps top eigenpair dominant and
  // roughly doubles convergence rate; per-matvec scale 1/16384 bounds
  // growth at (lambda-2500)/16384 <= ~0.17 so ||v||^2 never overflows.
  if(tid<64) v[tid]=((tid*2654435761u)>>13&1)? (1.f+0.01f*(float)tid) : (-1.f-0.01f*(float)tid);
  __syncthreads();
  for(int blk=0; blk<32; ++blk){
    for(int s8=0; s8<8; ++s8){
      float a=0;
      if(tid<64){
        float a0=0,a1=0,a2=0,a3=0;
        for(int e=0;e<64;e+=4){
          a0+=G[e][tid]*v[e];   a1+=G[e+1][tid]*v[e+1];
          a2+=G[e+2][tid]*v[e+2]; a3+=G[e+3][tid]*v[e+3];
        }
        a=(a0+a1)+(a2+a3) - 2500.f*v[tid];
        a *= 6.103515625e-5f;   // 1/16384
      }
      __syncthreads();
      if(tid<64) v[tid]=a;
      __syncthreads();
    }
    float nn=bsum((tid<64)?v[tid]*v[tid]:0.f,sr);
    float inv=rsqrtf(nn+1e-30f);
    if(tid<64) v[tid]*=inv;
    __syncthreads();
  }
  float a=0;
  if(tid<64){
    for(int e=0;e<64;e++) a+=G[e][tid]*v[e];
    a*=v[tid];
  }
  float lam=bsum((tid<64)?a:0.f,sr);
  float tr=bsum((tid<64)?G[tid][tid]:0.f,sr);
  if(tid==0) out[b*17+16]=lam/tr;
}

extern "C" void kernel_launch(void* const* d_in, const int* in_sizes, int n_in,
                              void* d_out, int out_size){
  const float* x =(const float*)d_in[0];
  const float* mk=(const float*)d_in[1];
  float* out=(float*)d_out;
  k1<<<BB,256>>>(x,mk,out);
  k2<<<dim3(BB,32),256>>>(x);
  k3<<<dim3(BB,3),256>>>(out);
  k4<<<BB,512>>>(out);
  k5<<<BB,256>>>(x,out);
}